// round 3
// baseline (speedup 1.0000x reference)
#include <cuda_runtime.h>
#include <cstdint>

#define NTHREADS 512

// Problem constants
#define T_CO 16
#define BATCH 16
#define NH 28
#define NW 28
#define CCH 64
#define KCH 64
#define ROW_FLOATS (NW * CCH)                  // 1792
#define WEIGHT_T_FLOATS (CCH * KCH)            // 4096
#define TRANS_T_STRIDE (BATCH * NH * NW * CCH) // 802816
#define TRANS_B_STRIDE (NH * NW * CCH)         // 50176

// Shared memory: mix[16][28][32] floats = 14336 floats = 56 KB (per CTA, 2 CTAs/SM)
#define MIX_FLOATS (T_CO * NW * 32)
#define SMEM_BYTES (MIX_FLOATS * 4)            // 57344

__device__ __forceinline__ void fma2(unsigned long long& d,
                                     unsigned long long a,
                                     unsigned long long b) {
    asm volatile("fma.rn.f32x2 %0, %1, %2, %0;" : "+l"(d) : "l"(a), "l"(b));
}

__device__ __forceinline__ unsigned long long dup2(float x) {
    unsigned long long r;
    asm("mov.b64 %0, {%1, %1};" : "=l"(r) : "f"(x));
    return r;
}

__device__ __forceinline__ float2 f2add(float2 a, float2 b) { return make_float2(a.x + b.x, a.y + b.y); }
__device__ __forceinline__ float2 f2sub(float2 a, float2 b) { return make_float2(a.x - b.x, a.y - b.y); }

__global__ void __launch_bounds__(NTHREADS, 2)
iwht2_kernel(const float* __restrict__ tr1, const float* __restrict__ tr2,
             const float* __restrict__ w1,  const float* __restrict__ w2,
             const float* __restrict__ b1,  const float* __restrict__ b2,
             float* __restrict__ out, size_t out_stream_stride)
{
    extern __shared__ float mix[];   // [t][w][32] floats : t*896 + w*32 + kf

    // CTA = (s, b, h, khalf); khalf fastest so sibling CTAs share trans via L2
    const int bi    = blockIdx.x;
    const int khalf = bi & 1;
    const int h     = (bi >> 1) % NH;
    const int b     = (bi >> 1) / NH % BATCH;
    const int s     = bi / (2 * NH * BATCH);

    const float* tr = s ? tr2 : tr1;
    const float* wt = s ? w2  : w1;
    const float* bs = s ? b2  : b1;
    float* outp = out + (size_t)s * out_stream_stride;

    const int tid  = threadIdx.x;
    const int t    = tid >> 5;            // warp -> coefficient
    const int lane = tid & 31;
    const int rg   = lane >> 3;           // 0..3 : rows rg*7 .. rg*7+6
    const int kg   = lane & 7;            // k floats [khalf*32 + kg*4, +4)

    // ---- GEMM: mixed[t, w, kslice] = sum_c trans[t,w,c] * W[t,c,kslice] ----
    {
        const float* tA = tr + (size_t)t * TRANS_T_STRIDE
                             + (size_t)b * TRANS_B_STRIDE
                             + (size_t)h * ROW_FLOATS
                             + (rg * 7) * CCH;
        const float* wB = wt + (size_t)t * WEIGHT_T_FLOATS + khalf * 32 + kg * 4;

        unsigned long long acc[7][2];
        #pragma unroll
        for (int r = 0; r < 7; r++) { acc[r][0] = 0ULL; acc[r][1] = 0ULL; }

        #pragma unroll 4
        for (int c4 = 0; c4 < 16; c4++) {
            // weights for 4 consecutive c (each 16B coalesced across kg lanes)
            ulonglong2 wv0 = *(const ulonglong2*)(wB + (4 * c4 + 0) * KCH);
            ulonglong2 wv1 = *(const ulonglong2*)(wB + (4 * c4 + 1) * KCH);
            ulonglong2 wv2 = *(const ulonglong2*)(wB + (4 * c4 + 2) * KCH);
            ulonglong2 wv3 = *(const ulonglong2*)(wB + (4 * c4 + 3) * KCH);
            #pragma unroll
            for (int r = 0; r < 7; r++) {
                float4 tv = *(const float4*)(tA + r * CCH + c4 * 4);
                unsigned long long a0 = dup2(tv.x);
                fma2(acc[r][0], a0, wv0.x); fma2(acc[r][1], a0, wv0.y);
                unsigned long long a1 = dup2(tv.y);
                fma2(acc[r][0], a1, wv1.x); fma2(acc[r][1], a1, wv1.y);
                unsigned long long a2 = dup2(tv.z);
                fma2(acc[r][0], a2, wv2.x); fma2(acc[r][1], a2, wv2.y);
                unsigned long long a3 = dup2(tv.w);
                fma2(acc[r][0], a3, wv3.x); fma2(acc[r][1], a3, wv3.y);
            }
        }

        // store to mix[t][row][kg*4..kg*4+4)
        #pragma unroll
        for (int r = 0; r < 7; r++) {
            int row = rg * 7 + r;
            *(ulonglong2*)(mix + t * 896 + row * 32 + kg * 4) =
                make_ulonglong2(acc[r][0], acc[r][1]);
        }
    }

    __syncthreads();

    // ---- combine: inverse 2D 4-pt WHT over t = 4u+v, scale 1/16, + bias ----
    // ep = w(28) x kpair(16) = 448 threads active
    if (tid < 448) {
        const int w  = tid >> 4;
        const int kp = tid & 15;
        const float2* mixf2 = (const float2*)mix;

        float2 m[16];
        #pragma unroll
        for (int tt = 0; tt < 16; tt++) m[tt] = mixf2[tt * 448 + w * 16 + kp];

        // stage 1 over v (in place)
        #pragma unroll
        for (int u = 0; u < 4; u++) {
            float2 m0 = m[4*u], m1 = m[4*u+1], m2 = m[4*u+2], m3 = m[4*u+3];
            float2 s0 = f2add(m0, m1), d0 = f2sub(m0, m1);
            float2 s1 = f2add(m2, m3), d1 = f2sub(m2, m3);
            m[4*u + 0] = f2add(s0, s1);
            m[4*u + 1] = f2add(d0, d1);
            m[4*u + 2] = f2sub(s0, s1);
            m[4*u + 3] = f2sub(d0, d1);
        }

        const float2 bv = ((const float2*)bs)[khalf * 16 + kp];
        float* op = outp + (size_t)b * (112 * 112 * 64)
                         + (size_t)h * (4 * 112 * 64)
                         + (size_t)w * (4 * 64)
                         + khalf * 32 + 2 * kp;

        // stage 2 over u
        #pragma unroll
        for (int j = 0; j < 4; j++) {
            float2 r0 = m[j], r1 = m[4 + j], r2 = m[8 + j], r3 = m[12 + j];
            float2 s0 = f2add(r0, r1), d0 = f2sub(r0, r1);
            float2 s1 = f2add(r2, r3), d1 = f2sub(r2, r3);
            float2 o0 = f2add(s0, s1);
            float2 o1 = f2add(d0, d1);
            float2 o2 = f2sub(s0, s1);
            float2 o3 = f2sub(d0, d1);
            float2 v0 = make_float2(fmaf(o0.x, 0.0625f, bv.x), fmaf(o0.y, 0.0625f, bv.y));
            float2 v1 = make_float2(fmaf(o1.x, 0.0625f, bv.x), fmaf(o1.y, 0.0625f, bv.y));
            float2 v2 = make_float2(fmaf(o2.x, 0.0625f, bv.x), fmaf(o2.y, 0.0625f, bv.y));
            float2 v3 = make_float2(fmaf(o3.x, 0.0625f, bv.x), fmaf(o3.y, 0.0625f, bv.y));
            *reinterpret_cast<float2*>(op + 0 * 7168 + j * 64) = v0;
            *reinterpret_cast<float2*>(op + 1 * 7168 + j * 64) = v1;
            *reinterpret_cast<float2*>(op + 2 * 7168 + j * 64) = v2;
            *reinterpret_cast<float2*>(op + 3 * 7168 + j * 64) = v3;
        }
    }
}

extern "C" void kernel_launch(void* const* d_in, const int* in_sizes, int n_in,
                              void* d_out, int out_size) {
    (void)in_sizes; (void)n_in;
    const float* tr1 = (const float*)d_in[0];
    const float* tr2 = (const float*)d_in[1];
    const float* w1  = (const float*)d_in[2];
    const float* w2  = (const float*)d_in[3];
    const float* b1  = (const float*)d_in[4];
    const float* b2  = (const float*)d_in[5];
    float* out = (float*)d_out;

    cudaFuncSetAttribute(iwht2_kernel,
                         cudaFuncAttributeMaxDynamicSharedMemorySize, SMEM_BYTES);

    size_t stream_stride = (size_t)out_size / 2;   // out1 then out2
    iwht2_kernel<<<2 * BATCH * NH * 2, NTHREADS, SMEM_BYTES>>>(
        tr1, tr2, w1, w2, b1, b2, out, stream_stride);
}

// round 4
// speedup vs baseline: 1.0962x; 1.0962x over previous
#include <cuda_runtime.h>
#include <cstdint>

#define NTHREADS 1024

// Problem constants
#define T_CO 16
#define BATCH 16
#define NH 28
#define NW 28
#define CCH 64
#define KCH 64
#define ROW_FLOATS (NW * CCH)                  // 1792 floats per (t) tile
#define WEIGHT_T_FLOATS (CCH * KCH)            // 4096
#define TRANS_T_STRIDE (BATCH * NH * NW * CCH) // 802816
#define TRANS_B_STRIDE (NH * NW * CCH)         // 50176

// Shared memory (floats):
// trs : [16][28][64]  (112 KB)  trans, XOR-swizzled float4 segments
// mix : [16][28][64]  (112 KB)  mixed coefficients, same swizzle
#define TRS_OFF 0
#define MIX_OFF 28672
#define SMEM_FLOATS (MIX_OFF + 28672)
#define SMEM_BYTES (SMEM_FLOATS * 4)           // 229376

__device__ __forceinline__ void fma2(unsigned long long& d,
                                     unsigned long long a,
                                     unsigned long long b) {
    asm volatile("fma.rn.f32x2 %0, %1, %2, %0;" : "+l"(d) : "l"(a), "l"(b));
}

__device__ __forceinline__ unsigned long long dup2(float x) {
    unsigned long long r;
    asm("mov.b64 %0, {%1, %1};" : "=l"(r) : "f"(x));
    return r;
}

__device__ __forceinline__ void cp16(uint32_t saddr, const void* g) {
    asm volatile("cp.async.cg.shared.global [%0], [%1], 16;" :: "r"(saddr), "l"(g));
}

__device__ __forceinline__ float2 f2add(float2 a, float2 b) { return make_float2(a.x + b.x, a.y + b.y); }
__device__ __forceinline__ float2 f2sub(float2 a, float2 b) { return make_float2(a.x - b.x, a.y - b.y); }

__global__ void __launch_bounds__(NTHREADS, 1)
iwht2_kernel(const float* __restrict__ tr1, const float* __restrict__ tr2,
             const float* __restrict__ w1,  const float* __restrict__ w2,
             const float* __restrict__ b1,  const float* __restrict__ b2,
             float* __restrict__ out, size_t out_stream_stride)
{
    extern __shared__ float sm[];
    float* trs = sm + TRS_OFF;
    float* mix = sm + MIX_OFF;

    // CTA = (s, b, h)
    const int bi = blockIdx.x;
    const int s  = bi / (BATCH * NH);
    const int rem = bi - s * (BATCH * NH);
    const int b  = rem / NH;
    const int h  = rem - b * NH;

    const float* tr = s ? tr2 : tr1;
    const float* wt = s ? w2  : w1;
    const float* bs = s ? b2  : b1;
    float* outp = out + (size_t)s * out_stream_stride;

    const int tid   = threadIdx.x;
    const int w     = tid >> 5;           // warp 0..31
    const int t     = w >> 1;             // coefficient 0..15
    const int khalf = w & 1;              // k half
    const int lane  = tid & 31;
    const int rg    = lane >> 3;          // rows rg*7 .. rg*7+6
    const int kg    = lane & 7;           // k floats khalf*32 + kg*4 .. +4

    const float* trbase = tr + (size_t)b * TRANS_B_STRIDE + (size_t)h * ROW_FLOATS;

    // ---- stage this pair's trans tile (7 KB) into swizzled smem ----
    {
        const float4* gsrc = (const float4*)(trbase + (size_t)t * TRANS_T_STRIDE);
        float* tile = trs + t * ROW_FLOATS;
        #pragma unroll
        for (int i = 0; i < 7; i++) {
            int idx = khalf * 224 + i * 32 + lane;   // float4 index 0..447
            int row = idx >> 4;
            int c4  = idx & 15;
            float* dst = tile + row * 64 + ((c4 ^ (row & 3)) << 2);
            cp16((uint32_t)__cvta_generic_to_shared(dst), gsrc + idx);
        }
        asm volatile("cp.async.commit_group;");
        asm volatile("cp.async.wait_group 0;" ::: "memory");
        // pair barrier: both khalf warps of this t
        asm volatile("bar.sync %0, 64;" :: "r"(t) : "memory");
    }

    // ---- GEMM: mixed[t, row, kslice] = sum_c trans[t,row,c] * W[t,c,kslice] ----
    {
        const float* tile = trs + t * ROW_FLOATS;
        const float* wB = wt + (size_t)t * WEIGHT_T_FLOATS + khalf * 32 + kg * 4;

        unsigned long long acc[7][2];
        #pragma unroll
        for (int r = 0; r < 7; r++) { acc[r][0] = 0ULL; acc[r][1] = 0ULL; }

        #pragma unroll 4
        for (int c4 = 0; c4 < 16; c4++) {
            ulonglong2 wv0 = *(const ulonglong2*)(wB + (4 * c4 + 0) * KCH);
            ulonglong2 wv1 = *(const ulonglong2*)(wB + (4 * c4 + 1) * KCH);
            ulonglong2 wv2 = *(const ulonglong2*)(wB + (4 * c4 + 2) * KCH);
            ulonglong2 wv3 = *(const ulonglong2*)(wB + (4 * c4 + 3) * KCH);
            #pragma unroll
            for (int r = 0; r < 7; r++) {
                int row = rg * 7 + r;
                float4 tv = *(const float4*)(tile + row * 64 + ((c4 ^ (row & 3)) << 2));
                unsigned long long a0 = dup2(tv.x);
                fma2(acc[r][0], a0, wv0.x); fma2(acc[r][1], a0, wv0.y);
                unsigned long long a1 = dup2(tv.y);
                fma2(acc[r][0], a1, wv1.x); fma2(acc[r][1], a1, wv1.y);
                unsigned long long a2 = dup2(tv.z);
                fma2(acc[r][0], a2, wv2.x); fma2(acc[r][1], a2, wv2.y);
                unsigned long long a3 = dup2(tv.w);
                fma2(acc[r][0], a3, wv3.x); fma2(acc[r][1], a3, wv3.y);
            }
        }

        // store to swizzled mix
        #pragma unroll
        for (int r = 0; r < 7; r++) {
            int row = rg * 7 + r;
            int seg = (khalf * 8 + kg) ^ (row & 3);
            *(ulonglong2*)(mix + t * ROW_FLOATS + row * 64 + (seg << 2)) =
                make_ulonglong2(acc[r][0], acc[r][1]);
        }
    }

    __syncthreads();

    // ---- combine: inverse 2D 4-pt WHT over t = 4u+v, scale 1/16, + bias ----
    if (tid < 896) {
        const int wrow = tid >> 5;        // 0..27 spatial w
        const int kp   = tid & 31;        // k pair (k = 2*kp)
        const int segx = ((kp >> 1) ^ (wrow & 3)) << 2;
        const int moff = wrow * 64 + segx + (kp & 1) * 2;   // float offset within tile

        float2 m[16];
        #pragma unroll
        for (int tt = 0; tt < 16; tt++)
            m[tt] = *(const float2*)(mix + tt * ROW_FLOATS + moff);

        // stage 1 over v (in place)
        #pragma unroll
        for (int u = 0; u < 4; u++) {
            float2 m0 = m[4*u], m1 = m[4*u+1], m2 = m[4*u+2], m3 = m[4*u+3];
            float2 s0 = f2add(m0, m1), d0 = f2sub(m0, m1);
            float2 s1 = f2add(m2, m3), d1 = f2sub(m2, m3);
            m[4*u + 0] = f2add(s0, s1);
            m[4*u + 1] = f2add(d0, d1);
            m[4*u + 2] = f2sub(s0, s1);
            m[4*u + 3] = f2sub(d0, d1);
        }

        const float2 bv = ((const float2*)bs)[kp];
        float* op = outp + (size_t)b * (112 * 112 * 64)
                         + (size_t)h * (4 * 112 * 64)
                         + (size_t)wrow * (4 * 64)
                         + 2 * kp;

        // stage 2 over u
        #pragma unroll
        for (int j = 0; j < 4; j++) {
            float2 r0 = m[j], r1 = m[4 + j], r2 = m[8 + j], r3 = m[12 + j];
            float2 s0 = f2add(r0, r1), d0 = f2sub(r0, r1);
            float2 s1 = f2add(r2, r3), d1 = f2sub(r2, r3);
            float2 o0 = f2add(s0, s1);
            float2 o1 = f2add(d0, d1);
            float2 o2 = f2sub(s0, s1);
            float2 o3 = f2sub(d0, d1);
            float2 v0 = make_float2(fmaf(o0.x, 0.0625f, bv.x), fmaf(o0.y, 0.0625f, bv.y));
            float2 v1 = make_float2(fmaf(o1.x, 0.0625f, bv.x), fmaf(o1.y, 0.0625f, bv.y));
            float2 v2 = make_float2(fmaf(o2.x, 0.0625f, bv.x), fmaf(o2.y, 0.0625f, bv.y));
            float2 v3 = make_float2(fmaf(o3.x, 0.0625f, bv.x), fmaf(o3.y, 0.0625f, bv.y));
            *reinterpret_cast<float2*>(op + 0 * 7168 + j * 64) = v0;
            *reinterpret_cast<float2*>(op + 1 * 7168 + j * 64) = v1;
            *reinterpret_cast<float2*>(op + 2 * 7168 + j * 64) = v2;
            *reinterpret_cast<float2*>(op + 3 * 7168 + j * 64) = v3;
        }
    }
}

extern "C" void kernel_launch(void* const* d_in, const int* in_sizes, int n_in,
                              void* d_out, int out_size) {
    (void)in_sizes; (void)n_in;
    const float* tr1 = (const float*)d_in[0];
    const float* tr2 = (const float*)d_in[1];
    const float* w1  = (const float*)d_in[2];
    const float* w2  = (const float*)d_in[3];
    const float* b1  = (const float*)d_in[4];
    const float* b2  = (const float*)d_in[5];
    float* out = (float*)d_out;

    cudaFuncSetAttribute(iwht2_kernel,
                         cudaFuncAttributeMaxDynamicSharedMemorySize, SMEM_BYTES);

    size_t stream_stride = (size_t)out_size / 2;   // out1 then out2
    iwht2_kernel<<<2 * BATCH * NH, NTHREADS, SMEM_BYTES>>>(
        tr1, tr2, w1, w2, b1, b2, out, stream_stride);
}

// round 6
// speedup vs baseline: 1.6911x; 1.5428x over previous
#include <cuda_runtime.h>
#include <cuda_bf16.h>
#include <cstdint>

// ---------------- problem constants ----------------
#define T_CO 16
#define BATCH 16
#define NH 28
#define NW 28
#define CCH 64
#define KCH 64
#define ROW_FLOATS (NW * CCH)                  // 1792
#define TRANS_T_STRIDE (BATCH * NH * NW * CCH) // 802816
#define TRANS_B_STRIDE (NH * NW * CCH)         // 50176

#define NTHREADS 512

// per-t smem slot (bytes): A frags (hi 4096 + lo 4096) during GEMM,
// then reused as mix[t] (28 rows x 288B = 8032B)
#define SLOT 8192
#define SMEM_BYTES (T_CO * SLOT)               // 131072
#define MIX_ROW 288                            // 72 floats per mix row

// ---------------- weight fragments (prepacked) ----------------
// layout [s][t][phys 8][nt 8][lane 32][2] b32 ; phys 0-3 = Bhi ktiles, 4-7 = Blo
__device__ uint32_t g_wfrag[2 * T_CO * 8 * 8 * 64];   // 512 KB

__device__ __forceinline__ uint32_t pack_bf16x2(float lo_elem, float hi_elem) {
    // returns {upper16 = bf16(hi_elem), lower16 = bf16(lo_elem)}
    uint32_t r;
    asm("cvt.rn.bf16x2.f32 %0, %1, %2;" : "=r"(r) : "f"(hi_elem), "f"(lo_elem));
    return r;
}

__global__ void prep_weights(const float* __restrict__ w1, const float* __restrict__ w2) {
    int idx = blockIdx.x * 256 + threadIdx.x;      // 131072 total
    int r    = idx & 1;
    int lane = (idx >> 1) & 31;
    int nt   = (idx >> 6) & 7;
    int phys = (idx >> 9) & 7;
    int t    = (idx >> 12) & 15;
    int s    = idx >> 16;
    const float* w = s ? w2 : w1;
    int kchan = nt * 8 + (lane >> 2);
    int c     = (phys & 3) * 16 + (lane & 3) * 2 + r * 8;
    float v0 = w[(t * 64 + c) * 64 + kchan];
    float v1 = w[(t * 64 + c + 1) * 64 + kchan];
    if (phys >= 4) {   // lo residual tiles
        v0 = v0 - __bfloat162float(__float2bfloat16_rn(v0));
        v1 = v1 - __bfloat162float(__float2bfloat16_rn(v1));
    }
    g_wfrag[idx] = pack_bf16x2(v0, v1);
}

// ---------------- main kernel ----------------
__device__ __forceinline__ float2 f2add(float2 a, float2 b) { return make_float2(a.x + b.x, a.y + b.y); }
__device__ __forceinline__ float2 f2sub(float2 a, float2 b) { return make_float2(a.x - b.x, a.y - b.y); }

#define MMA16816(d, a, b0, b1)                                               \
    asm("mma.sync.aligned.m16n8k16.row.col.f32.bf16.bf16.f32 "               \
        "{%0,%1,%2,%3},{%4,%5,%6,%7},{%8,%9},{%0,%1,%2,%3};"                 \
        : "+f"((d)[0]), "+f"((d)[1]), "+f"((d)[2]), "+f"((d)[3])             \
        : "r"((a).x), "r"((a).y), "r"((a).z), "r"((a).w), "r"(b0), "r"(b1))

__global__ void __launch_bounds__(NTHREADS, 1)
iwht2_mma_kernel(const float* __restrict__ tr1, const float* __restrict__ tr2,
                 const float* __restrict__ b1,  const float* __restrict__ b2,
                 float* __restrict__ out, size_t out_stream_stride)
{
    extern __shared__ char smc[];

    const int bi  = blockIdx.x;
    const int s   = bi / (BATCH * NH);
    const int rem = bi - s * (BATCH * NH);
    const int b   = rem / NH;
    const int h   = rem - b * NH;

    const float* tr = s ? tr2 : tr1;
    const float* bs = s ? b2  : b1;
    float* outp = out + (size_t)s * out_stream_stride;

    const int tid  = threadIdx.x;
    const int t    = tid >> 5;
    const int lane = tid & 31;
    const int g    = lane >> 2;     // group id (rows)
    const int tg   = lane & 3;      // thread-in-group (cols)
    char* tslot = smc + t * SLOT;

    // ---- stage A: trans tile -> bf16 hi/lo fragments in smem ----
    {
        const float4* gsrc = (const float4*)(tr + (size_t)b * TRANS_B_STRIDE
                                                + (size_t)h * ROW_FLOATS
                                                + (size_t)t * TRANS_T_STRIDE);
        #pragma unroll
        for (int i = 0; i < 14; i++) {
            int idx = i * 32 + lane;           // 0..447 float4s
            int row = idx >> 4;                // 0..27
            int c4  = idx & 15;
            float4 v = __ldg(gsrc + idx);

            int mt  = row >> 4;
            int rp  = row & 15;
            int gg  = rp & 7;
            int rb  = rp >> 3;                 // 0 -> a0/a2, 1 -> a1/a3
            int kt  = c4 >> 2;
            int cpp = (c4 & 3) * 4;            // within-tile col base {0,4,8,12}
            int areg = rb + ((cpp >= 8) ? 2 : 0);
            int L0   = gg * 4 + ((cpp & 7) >> 1);

            uint32_t h0 = pack_bf16x2(v.x, v.y);
            uint32_t h1 = pack_bf16x2(v.z, v.w);
            float lx = v.x - __uint_as_float(h0 << 16);
            float ly = v.y - __uint_as_float(h0 & 0xffff0000u);
            float lz = v.z - __uint_as_float(h1 << 16);
            float lw = v.w - __uint_as_float(h1 & 0xffff0000u);
            uint32_t l0 = pack_bf16x2(lx, ly);
            uint32_t l1 = pack_bf16x2(lz, lw);

            uint32_t off0 = mt * 2048 + kt * 512 + (((L0)     ^ (kt << 1)) << 4) + areg * 4;
            uint32_t off1 = mt * 2048 + kt * 512 + (((L0 + 1) ^ (kt << 1)) << 4) + areg * 4;
            *(uint32_t*)(tslot + off0)        = h0;
            *(uint32_t*)(tslot + off1)        = h1;
            *(uint32_t*)(tslot + 4096 + off0) = l0;
            *(uint32_t*)(tslot + 4096 + off1) = l1;
        }
    }
    __syncwarp();

    // ---- GEMM: D(28x64) = A''(28x192) x B''(192x64), 3-term bf16 split ----
    float acc[2][8][4];
    #pragma unroll
    for (int mt = 0; mt < 2; mt++)
        #pragma unroll
        for (int nt = 0; nt < 8; nt++)
            #pragma unroll
            for (int j = 0; j < 4; j++) acc[mt][nt][j] = 0.0f;

    const uint32_t* gw = g_wfrag + (size_t)(s * T_CO + t) * (8 * 512);

    #pragma unroll
    for (int ki = 0; ki < 12; ki++) {
        const int hl   = (ki >= 8) ? 1 : 0;          // ki 0-7: Ahi, 8-11: Alo
        const int ktp  = ki & 3;
        const int phys = (ki < 8) ? ki : (ki - 8);   // B: hi(0-3), lo(4-7), hi(0-3)

        uint4 A0 = *(const uint4*)(tslot + hl * 4096 + 0    + ktp * 512
                                   + ((lane ^ (ktp << 1)) << 4));
        uint4 A1 = *(const uint4*)(tslot + hl * 4096 + 2048 + ktp * 512
                                   + ((lane ^ (ktp << 1)) << 4));
        #pragma unroll
        for (int nt = 0; nt < 8; nt++) {
            uint2 bv = *(const uint2*)(gw + (phys * 8 + nt) * 64 + lane * 2);
            MMA16816(acc[0][nt], A0, bv.x, bv.y);
            MMA16816(acc[1][nt], A1, bv.x, bv.y);
        }
    }

    // ---- write D into mix slot (reuses this warp's A region) ----
    #pragma unroll
    for (int mt = 0; mt < 2; mt++) {
        #pragma unroll
        for (int nt = 0; nt < 8; nt++) {
            int row0 = mt * 16 + g;
            int kp   = nt * 4 + tg;
            *(float2*)(tslot + row0 * MIX_ROW + kp * 8) =
                make_float2(acc[mt][nt][0], acc[mt][nt][1]);
            int row1 = row0 + 8;
            if (row1 < 28)
                *(float2*)(tslot + row1 * MIX_ROW + kp * 8) =
                    make_float2(acc[mt][nt][2], acc[mt][nt][3]);
        }
    }
    __syncthreads();

    // ---- combine: inverse 2D 4-pt WHT over t = 4u+v, scale 1/16, + bias ----
    #pragma unroll
    for (int it = 0; it < 2; it++) {
        int ep = it * NTHREADS + tid;          // 0..895 = w(28) x kpair(32)
        if (ep < 896) {
            const int wrow = ep >> 5;
            const int kp   = ep & 31;

            float2 m[16];
            #pragma unroll
            for (int tt = 0; tt < 16; tt++)
                m[tt] = *(const float2*)(smc + tt * SLOT + wrow * MIX_ROW + kp * 8);

            #pragma unroll
            for (int u = 0; u < 4; u++) {
                float2 m0 = m[4*u], m1 = m[4*u+1], m2 = m[4*u+2], m3 = m[4*u+3];
                float2 s0 = f2add(m0, m1), d0 = f2sub(m0, m1);
                float2 s1 = f2add(m2, m3), d1 = f2sub(m2, m3);
                m[4*u + 0] = f2add(s0, s1);
                m[4*u + 1] = f2add(d0, d1);
                m[4*u + 2] = f2sub(s0, s1);
                m[4*u + 3] = f2sub(d0, d1);
            }

            const float2 bv = ((const float2*)bs)[kp];
            float* op = outp + (size_t)b * (112 * 112 * 64)
                             + (size_t)h * (4 * 112 * 64)
                             + (size_t)wrow * (4 * 64)
                             + 2 * kp;

            #pragma unroll
            for (int j = 0; j < 4; j++) {
                float2 r0 = m[j], r1 = m[4 + j], r2 = m[8 + j], r3 = m[12 + j];
                float2 s0 = f2add(r0, r1), d0 = f2sub(r0, r1);
                float2 s1 = f2add(r2, r3), d1 = f2sub(r2, r3);
                float2 o0 = f2add(s0, s1);
                float2 o1 = f2add(d0, d1);
                float2 o2 = f2sub(s0, s1);
                float2 o3 = f2sub(d0, d1);
                float2 v0 = make_float2(fmaf(o0.x, 0.0625f, bv.x), fmaf(o0.y, 0.0625f, bv.y));
                float2 v1 = make_float2(fmaf(o1.x, 0.0625f, bv.x), fmaf(o1.y, 0.0625f, bv.y));
                float2 v2 = make_float2(fmaf(o2.x, 0.0625f, bv.x), fmaf(o2.y, 0.0625f, bv.y));
                float2 v3 = make_float2(fmaf(o3.x, 0.0625f, bv.x), fmaf(o3.y, 0.0625f, bv.y));
                *reinterpret_cast<float2*>(op + 0 * 7168 + j * 64) = v0;
                *reinterpret_cast<float2*>(op + 1 * 7168 + j * 64) = v1;
                *reinterpret_cast<float2*>(op + 2 * 7168 + j * 64) = v2;
                *reinterpret_cast<float2*>(op + 3 * 7168 + j * 64) = v3;
            }
        }
    }
}

extern "C" void kernel_launch(void* const* d_in, const int* in_sizes, int n_in,
                              void* d_out, int out_size) {
    (void)in_sizes; (void)n_in;
    const float* tr1 = (const float*)d_in[0];
    const float* tr2 = (const float*)d_in[1];
    const float* w1  = (const float*)d_in[2];
    const float* w2  = (const float*)d_in[3];
    const float* b1  = (const float*)d_in[4];
    const float* b2  = (const float*)d_in[5];
    float* out = (float*)d_out;

    prep_weights<<<512, 256>>>(w1, w2);

    cudaFuncSetAttribute(iwht2_mma_kernel,
                         cudaFuncAttributeMaxDynamicSharedMemorySize, SMEM_BYTES);
    size_t stream_stride = (size_t)out_size / 2;   // out1 then out2
    iwht2_mma_kernel<<<2 * BATCH * NH, NTHREADS, SMEM_BYTES>>>(
        tr1, tr2, b1, b2, out, stream_stride);
}